// round 16
// baseline (speedup 1.0000x reference)
#include <cuda_runtime.h>
#include <cuda_fp16.h>
#include <cstdint>

#define MTOK  2048
#define DDIM  1024
#define IDIM  2048
#define ENUM  8
#define NPAIR 4096   // MTOK * TOPK

// ---------------- scratch (no allocations allowed) ----------------
__device__ int    g_count[ENUM];
__device__ int    g_off[ENUM];
__device__ int    g_rowlist[NPAIR];                 // pair indices grouped by expert
__device__ __half g_act[(size_t)NPAIR * IDIM];      // 16 MB gate activations (fp16)
__device__ __half g_x16[(size_t)MTOK * DDIM];                    // 4 MB
__device__ __half g_w13h[(size_t)ENUM * 2 * IDIM * DDIM];        // 64 MB
__device__ __half g_w2h[(size_t)ENUM * DDIM * IDIM];             // 32 MB

// ---------------- helpers ----------------
__device__ __forceinline__ void mma16(float* c, const uint32_t* a, const uint32_t* b) {
    asm volatile(
        "mma.sync.aligned.m16n8k16.row.col.f32.f16.f16.f32 "
        "{%0,%1,%2,%3}, {%4,%5,%6,%7}, {%8,%9}, {%0,%1,%2,%3};\n"
        : "+f"(c[0]), "+f"(c[1]), "+f"(c[2]), "+f"(c[3])
        : "r"(a[0]), "r"(a[1]), "r"(a[2]), "r"(a[3]), "r"(b[0]), "r"(b[1]));
}
#define LDSM4(r0, r1, r2, r3, addr)                                        \
    asm volatile("ldmatrix.sync.aligned.m8n8.x4.shared.b16 {%0,%1,%2,%3}, [%4];" \
                 : "=r"(r0), "=r"(r1), "=r"(r2), "=r"(r3) : "r"(addr))
#define CP16(sm, gm) \
    asm volatile("cp.async.cg.shared.global [%0], [%1], 16;" :: "r"(sm), "l"(gm))
#define CP_COMMIT() asm volatile("cp.async.commit_group;")
#define CP_WAIT2()  asm volatile("cp.async.wait_group 2;")

// ---------------- prep: routing (block 0) + fp32->fp16 convert (blocks 1..N) ----
__device__ __forceinline__ void cvt4(const float* s, __half* d, size_t i) {
    float4 v = ((const float4*)s)[i];
    __half2* o = (__half2*)(d + 4 * i);
    o[0] = __floats2half2_rn(v.x, v.y);
    o[1] = __floats2half2_rn(v.z, v.w);
}
__global__ void prep_kernel(const int* __restrict__ idx,
                            const float* __restrict__ x,
                            const float* __restrict__ w13,
                            const float* __restrict__ w2) {
    if (blockIdx.x == 0) {
        // routing: counts -> offsets -> permutation (expert_indices is int32)
        __shared__ int sc[ENUM];
        __shared__ int scur[ENUM];
        int tid = threadIdx.x;
        if (tid < ENUM) sc[tid] = 0;
        __syncthreads();
        for (int p = tid; p < NPAIR; p += blockDim.x) atomicAdd(&sc[idx[p]], 1);
        __syncthreads();
        if (tid == 0) {
            int o = 0;
            for (int e = 0; e < ENUM; e++) {
                g_count[e] = sc[e]; g_off[e] = o; scur[e] = o; o += sc[e];
            }
        }
        __syncthreads();
        for (int p = tid; p < NPAIR; p += blockDim.x) {
            int pos = atomicAdd(&scur[idx[p]], 1);
            g_rowlist[pos] = p;
        }
    } else {
        size_t gid = (size_t)(blockIdx.x - 1) * blockDim.x + threadIdx.x;
        size_t gs  = (size_t)(gridDim.x - 1) * blockDim.x;
        for (size_t i = gid; i < (size_t)MTOK * DDIM / 4; i += gs)            cvt4(x,  g_x16,  i);
        for (size_t i = gid; i < (size_t)ENUM * 2 * IDIM * DDIM / 4; i += gs) cvt4(w13, g_w13h, i);
        for (size_t i = gid; i < (size_t)ENUM * DDIM * IDIM / 4; i += gs)     cvt4(w2, g_w2h,  i);
    }
}

// ncu captures the 4th launch: prep, dummy, dummy, GEMM1 <- profiled
__global__ void dummy_kernel() {}

// ---------------- GEMM1: h = x @ w13_e^T (both halves) + silu-gate ----------------
// CTA 128m x 128 gate-cols, BK=64, 4-stage cp.async, ks-pipelined fragments.
// Fast/slow mainloop: full tiles run branch-free; partial tiles skip MMA bursts
// for warp m-blocks entirely past cnt (recovers ~12% padding waste).
#define G1_SROW  72
#define G1_STGH  ((128 + 256) * G1_SROW)          // halves/stage = 27648
#define G1_STGB  (G1_STGH * 2)                    // 55296 B
#define G1_SMEM  (4 * G1_STGB)                    // 221184 B (< 227 KB cap)
__global__ __launch_bounds__(256) void gemm1_kernel() {
    extern __shared__ __half sm1[];
    int e     = blockIdx.z;
    int cnt   = g_count[e];
    int mbase = blockIdx.y * 128;
    if (mbase >= cnt) return;
    int nbase = blockIdx.x * 128;
    int off   = g_off[e];
    const char* xbase = (const char*)g_x16;
    const char* wbase = (const char*)(g_w13h + (size_t)e * 2 * IDIM * DDIM);

    int tid  = threadIdx.x;
    int lane = tid & 31, wp = tid >> 5;
    int wr = wp >> 2, wc = wp & 3;          // 2m x 4n warp grid
    int g  = lane >> 2, t = lane & 3;

    uint32_t sbase = (uint32_t)__cvta_generic_to_shared(sm1);

    // ---- cp.async fill metadata (u32 byte offsets; BK=64: 8 chunks/row) ----
    uint32_t a_goff[4], a_off[4];
#pragma unroll
    for (int i = 0; i < 4; i++) {
        int idx = tid + 256 * i, row = idx >> 3, c8 = idx & 7;
        int m = mbase + row;
        int tok = (m < cnt) ? (g_rowlist[off + m] >> 1) : 0;   // TOPK=2: token = pair>>1
        a_goff[i] = (uint32_t)(tok * DDIM + c8 * 8) * 2;
        a_off[i]  = (uint32_t)(row * G1_SROW + c8 * 8) * 2;
    }
    uint32_t b_goff[8], b_off[8];
#pragma unroll
    for (int i = 0; i < 8; i++) {
        int idx = tid + 256 * i, row = idx >> 3, c8 = idx & 7;
        b_goff[i] = (row < 128)
            ? (uint32_t)(((nbase + row) * DDIM + c8 * 8) * 2)
            : (uint32_t)((IDIM * DDIM + (size_t)(nbase + row - 128) * DDIM + c8 * 8) * 2);
        b_off[i] = (uint32_t)((128 + row) * G1_SROW + c8 * 8) * 2;
    }

#define G1_ISSUE(s, kt)                                                       \
    { uint32_t _sb = sbase + (s) * G1_STGB;                                   \
      uint32_t _k = (uint32_t)(kt) * 128;                                     \
      CP16(_sb + a_off[0], xbase + a_goff[0] + _k);                           \
      CP16(_sb + a_off[1], xbase + a_goff[1] + _k);                           \
      CP16(_sb + a_off[2], xbase + a_goff[2] + _k);                           \
      CP16(_sb + a_off[3], xbase + a_goff[3] + _k);                           \
      CP16(_sb + b_off[0], wbase + b_goff[0] + _k);                           \
      CP16(_sb + b_off[1], wbase + b_goff[1] + _k);                           \
      CP16(_sb + b_off[2], wbase + b_goff[2] + _k);                           \
      CP16(_sb + b_off[3], wbase + b_goff[3] + _k);                           \
      CP16(_sb + b_off[4], wbase + b_goff[4] + _k);                           \
      CP16(_sb + b_off[5], wbase + b_goff[5] + _k);                           \
      CP16(_sb + b_off[6], wbase + b_goff[6] + _k);                           \
      CP16(_sb + b_off[7], wbase + b_goff[7] + _k); }

    // ---- ldmatrix per-lane base addresses ----
    int lm = lane >> 3, ll = lane & 7;
    uint32_t a_lm[4], b1_lm[2], b3_lm[2];
#pragma unroll
    for (int mt = 0; mt < 4; mt++) {
        int row = wr * 64 + mt * 16 + (lm & 1) * 8 + ll;
        a_lm[mt] = (uint32_t)(row * G1_SROW + (lm >> 1) * 8) * 2;
    }
#pragma unroll
    for (int p = 0; p < 2; p++) {
        int row = wc * 32 + p * 16 + (lm >> 1) * 8 + ll;
        uint32_t o = (uint32_t)(row * G1_SROW + (lm & 1) * 8) * 2;
        b1_lm[p] = o + (uint32_t)(128 * G1_SROW) * 2;
        b3_lm[p] = o + (uint32_t)(256 * G1_SROW) * 2;
    }

    // double-buffered fragments
    uint32_t af[2][4][4], b1f[2][2][4], b3f[2][2][4];

#define G1_FRAGS(buf, sb, ko)                                                 \
    {                                                                         \
        _Pragma("unroll")                                                     \
        for (int mt = 0; mt < 4; mt++)                                        \
            LDSM4(af[buf][mt][0], af[buf][mt][1], af[buf][mt][2],             \
                  af[buf][mt][3], (sb) + a_lm[mt] + (ko));                    \
        _Pragma("unroll")                                                     \
        for (int p = 0; p < 2; p++) {                                         \
            LDSM4(b1f[buf][p][0], b1f[buf][p][1], b1f[buf][p][2],             \
                  b1f[buf][p][3], (sb) + b1_lm[p] + (ko));                    \
            LDSM4(b3f[buf][p][0], b3f[buf][p][1], b3f[buf][p][2],             \
                  b3f[buf][p][3], (sb) + b3_lm[p] + (ko));                    \
        }                                                                     \
    }

    float c[2][4][4][4];                     // [half][mt][nt][frag] = 128 regs
#pragma unroll
    for (int h = 0; h < 2; h++)
#pragma unroll
        for (int mt = 0; mt < 4; mt++)
#pragma unroll
            for (int nt = 0; nt < 4; nt++)
#pragma unroll
                for (int i = 0; i < 4; i++) c[h][mt][nt][i] = 0.f;

    const int nK = DDIM / 64;   // 16
    G1_ISSUE(0, 0) CP_COMMIT();
    G1_ISSUE(1, 1) CP_COMMIT();
    G1_ISSUE(2, 2) CP_COMMIT();

    bool mok[4];
#pragma unroll
    for (int mt = 0; mt < 4; mt++) mok[mt] = (mbase + wr * 64 + mt * 16) < cnt;

#define G1_MAINLOOP(CHECK)                                                    \
    for (int kt = 0; kt < nK; kt++) {                                         \
        CP_WAIT2();                                                           \
        __syncthreads();                                                      \
        uint32_t sb = sbase + (kt & 3) * G1_STGB;                             \
        G1_FRAGS(0, sb, 0)                                                    \
        if (kt + 3 < nK) { G1_ISSUE((kt + 3) & 3, kt + 3) }                   \
        CP_COMMIT();                                                          \
        _Pragma("unroll")                                                     \
        for (int ks = 0; ks < 4; ks++) {                                      \
            int cur = ks & 1;                                                 \
            if (ks < 3) { G1_FRAGS(cur ^ 1, sb, (uint32_t)(ks + 1) * 32) }    \
            _Pragma("unroll")                                                 \
            for (int mt = 0; mt < 4; mt++) {                                  \
                if ((CHECK) && !mok[mt]) continue;                            \
                _Pragma("unroll")                                             \
                for (int nt = 0; nt < 4; nt++) {                              \
                    const uint32_t* bb1 = &b1f[cur][nt >> 1][(nt & 1) * 2];   \
                    const uint32_t* bb3 = &b3f[cur][nt >> 1][(nt & 1) * 2];   \
                    mma16(c[0][mt][nt], af[cur][mt], bb1);                    \
                    mma16(c[1][mt][nt], af[cur][mt], bb3);                    \
                }                                                             \
            }                                                                 \
        }                                                                     \
    }

    if (mbase + 128 <= cnt) { G1_MAINLOOP(0) } else { G1_MAINLOOP(1) }

    // fused silu(x1)*x3 epilogue -> g_act (fp16, rows in grouped order)
    int rowbase = off + mbase;
#pragma unroll
    for (int mt = 0; mt < 4; mt++) {
        int r0 = wr * 64 + mt * 16 + g;
#pragma unroll
        for (int nt = 0; nt < 4; nt++) {
            int col = nbase + wc * 32 + nt * 8 + 2 * t;
            if (mbase + r0 < cnt) {
                float v1a = c[0][mt][nt][0], v3a = c[1][mt][nt][0];
                float v1b = c[0][mt][nt][1], v3b = c[1][mt][nt][1];
                float ga = v1a / (1.f + __expf(-v1a)) * v3a;
                float gb = v1b / (1.f + __expf(-v1b)) * v3b;
                *(__half2*)&g_act[(size_t)(rowbase + r0) * IDIM + col] =
                    __floats2half2_rn(ga, gb);
            }
            if (mbase + r0 + 8 < cnt) {
                float v1a = c[0][mt][nt][2], v3a = c[1][mt][nt][2];
                float v1b = c[0][mt][nt][3], v3b = c[1][mt][nt][3];
                float ga = v1a / (1.f + __expf(-v1a)) * v3a;
                float gb = v1b / (1.f + __expf(-v1b)) * v3b;
                *(__half2*)&g_act[(size_t)(rowbase + r0 + 8) * IDIM + col] =
                    __floats2half2_rn(ga, gb);
            }
        }
    }
}

// ---------------- GEMM2: out = g_act @ w2_e^T, scatter ----------------
// CTA 128m x 128n, BK=64, 4-stage cp.async, fast/slow mainloop like gemm1.
#define G2_SROW  72
#define G2_STGH  ((128 + 128) * G2_SROW)          // 18432 halves
#define G2_STGB  (G2_STGH * 2)                    // 36864 B
#define G2_SMEM  (4 * G2_STGB)                    // 147456 B
__global__ __launch_bounds__(256) void gemm2_kernel(float* __restrict__ out) {
    extern __shared__ __half sm2[];
    int e     = blockIdx.z;
    int cnt   = g_count[e];
    int mbase = blockIdx.y * 128;
    if (mbase >= cnt) return;
    int cbase = blockIdx.x * 128;
    int off   = g_off[e];
    const char* abase = (const char*)g_act;
    const char* wbase = (const char*)(g_w2h + (size_t)e * DDIM * IDIM);

    int tid  = threadIdx.x;
    int lane = tid & 31, wp = tid >> 5;
    int wr = wp >> 2, wc = wp & 3;
    int g  = lane >> 2, t = lane & 3;

    uint32_t sbase = (uint32_t)__cvta_generic_to_shared(sm2);

    uint32_t a_goff[4], a_off[4];
#pragma unroll
    for (int i = 0; i < 4; i++) {
        int idx = tid + 256 * i, row = idx >> 3, c8 = idx & 7;
        int ga = off + mbase + row;
        if (ga > NPAIR - 1) ga = NPAIR - 1;   // pad rows never stored
        a_goff[i] = (uint32_t)(((size_t)ga * IDIM + c8 * 8) * 2);
        a_off[i]  = (uint32_t)(row * G2_SROW + c8 * 8) * 2;
    }
    uint32_t b_goff[4], b_off[4];
#pragma unroll
    for (int i = 0; i < 4; i++) {
        int idx = tid + 256 * i, row = idx >> 3, c8 = idx & 7;
        b_goff[i] = (uint32_t)(((size_t)(cbase + row) * IDIM + c8 * 8) * 2);
        b_off[i]  = (uint32_t)((128 + row) * G2_SROW + c8 * 8) * 2;
    }

#define G2_ISSUE(s, kt)                                                       \
    { uint32_t _sb = sbase + (s) * G2_STGB;                                   \
      uint32_t _k = (uint32_t)(kt) * 128;                                     \
      CP16(_sb + a_off[0], abase + a_goff[0] + _k);                           \
      CP16(_sb + a_off[1], abase + a_goff[1] + _k);                           \
      CP16(_sb + a_off[2], abase + a_goff[2] + _k);                           \
      CP16(_sb + a_off[3], abase + a_goff[3] + _k);                           \
      CP16(_sb + b_off[0], wbase + b_goff[0] + _k);                           \
      CP16(_sb + b_off[1], wbase + b_goff[1] + _k);                           \
      CP16(_sb + b_off[2], wbase + b_goff[2] + _k);                           \
      CP16(_sb + b_off[3], wbase + b_goff[3] + _k); }

    int lm = lane >> 3, ll = lane & 7;
    uint32_t a_lm[4], b_lm[2];
#pragma unroll
    for (int mt = 0; mt < 4; mt++) {
        int row = wr * 64 + mt * 16 + (lm & 1) * 8 + ll;
        a_lm[mt] = (uint32_t)(row * G2_SROW + (lm >> 1) * 8) * 2;
    }
#pragma unroll
    for (int p = 0; p < 2; p++) {
        int row = wc * 32 + p * 16 + (lm >> 1) * 8 + ll;
        b_lm[p] = (uint32_t)((128 + row) * G2_SROW + (lm & 1) * 8) * 2;
    }

    uint32_t af[2][4][4], bf[2][2][4];

#define G2_FRAGS(buf, sb, ko)                                                 \
    {                                                                         \
        _Pragma("unroll")                                                     \
        for (int mt = 0; mt < 4; mt++)                                        \
            LDSM4(af[buf][mt][0], af[buf][mt][1], af[buf][mt][2],             \
                  af[buf][mt][3], (sb) + a_lm[mt] + (ko));                    \
        _Pragma("unroll")                                                     \
        for (int p = 0; p < 2; p++)                                           \
            LDSM4(bf[buf][p][0], bf[buf][p][1], bf[buf][p][2],                \
                  bf[buf][p][3], (sb) + b_lm[p] + (ko));                      \
    }

    float c[4][4][4];                        // [mt][nt][frag] = 64 regs
#pragma unroll
    for (int mt = 0; mt < 4; mt++)
#pragma unroll
        for (int nt = 0; nt < 4; nt++)
#pragma unroll
            for (int i = 0; i < 4; i++) c[mt][nt][i] = 0.f;

    const int nK = IDIM / 64;   // 32
    G2_ISSUE(0, 0) CP_COMMIT();
    G2_ISSUE(1, 1) CP_COMMIT();
    G2_ISSUE(2, 2) CP_COMMIT();

    bool mok[4];
#pragma unroll
    for (int mt = 0; mt < 4; mt++) mok[mt] = (mbase + wr * 64 + mt * 16) < cnt;

#define G2_MAINLOOP(CHECK)                                                    \
    for (int kt = 0; kt < nK; kt++) {                                         \
        CP_WAIT2();                                                           \
        __syncthreads();                                                      \
        uint32_t sb = sbase + (kt & 3) * G2_STGB;                             \
        G2_FRAGS(0, sb, 0)                                                    \
        if (kt + 3 < nK) { G2_ISSUE((kt + 3) & 3, kt + 3) }                   \
        CP_COMMIT();                                                          \
        _Pragma("unroll")                                                     \
        for (int ks = 0; ks < 4; ks++) {                                      \
            int cur = ks & 1;                                                 \
            if (ks < 3) { G2_FRAGS(cur ^ 1, sb, (uint32_t)(ks + 1) * 32) }    \
            _Pragma("unroll")                                                 \
            for (int mt = 0; mt < 4; mt++) {                                  \
                if ((CHECK) && !mok[mt]) continue;                            \
                _Pragma("unroll")                                             \
                for (int nt = 0; nt < 4; nt++) {                              \
                    const uint32_t* bb = &bf[cur][nt >> 1][(nt & 1) * 2];     \
                    mma16(c[mt][nt], af[cur][mt], bb);                        \
                }                                                             \
            }                                                                 \
        }                                                                     \
    }

    if (mbase + 128 <= cnt) { G2_MAINLOOP(0) } else { G2_MAINLOOP(1) }

    // scatter epilogue: out[pair][col] (fp32)
#pragma unroll
    for (int mt = 0; mt < 4; mt++) {
        int r = wr * 64 + mt * 16 + g;
#pragma unroll
        for (int nt = 0; nt < 4; nt++) {
            int col = cbase + wc * 32 + nt * 8 + 2 * t;
            if (mbase + r < cnt) {
                int pair = g_rowlist[off + mbase + r];
                *(float2*)&out[(size_t)pair * DDIM + col] =
                    make_float2(c[mt][nt][0], c[mt][nt][1]);
            }
            if (mbase + r + 8 < cnt) {
                int pair = g_rowlist[off + mbase + r + 8];
                *(float2*)&out[(size_t)pair * DDIM + col] =
                    make_float2(c[mt][nt][2], c[mt][nt][3]);
            }
        }
    }
}

// ---------------- launch ----------------
extern "C" void kernel_launch(void* const* d_in, const int* in_sizes, int n_in,
                              void* d_out, int out_size) {
    (void)in_sizes; (void)n_in; (void)out_size;
    const float* x   = (const float*)d_in[0];
    const float* w13 = (const float*)d_in[1];
    const float* w2  = (const float*)d_in[2];
    const int*   idx = (const int*)d_in[3];
    float* out = (float*)d_out;

    cudaFuncSetAttribute(gemm1_kernel, cudaFuncAttributeMaxDynamicSharedMemorySize, G1_SMEM);
    cudaFuncSetAttribute(gemm2_kernel, cudaFuncAttributeMaxDynamicSharedMemorySize, G2_SMEM);

    prep_kernel<<<1025, 256>>>(idx, x, w13, w2);   // block 0 routes, rest convert
    dummy_kernel<<<1, 32>>>();   // slot 2
    dummy_kernel<<<1, 32>>>();   // slot 3 -> gemm1 lands in profiled slot 4
    gemm1_kernel<<<dim3(IDIM / 128, NPAIR / 128, ENUM), 256, G1_SMEM>>>();
    gemm2_kernel<<<dim3(DDIM / 128, NPAIR / 128, ENUM), 256, G2_SMEM>>>(out);
}

// round 17
// speedup vs baseline: 1.0127x; 1.0127x over previous
#include <cuda_runtime.h>
#include <cuda_fp16.h>
#include <cstdint>

#define MTOK  2048
#define DDIM  1024
#define IDIM  2048
#define ENUM  8
#define NPAIR 4096   // MTOK * TOPK

// ---------------- scratch (no allocations allowed) ----------------
__device__ int    g_count[ENUM];
__device__ int    g_off[ENUM];
__device__ int    g_rowlist[NPAIR];                 // pair indices grouped by expert
__device__ __half g_act[(size_t)NPAIR * IDIM];      // 16 MB gate activations (fp16)
__device__ __half g_x16[(size_t)MTOK * DDIM];                    // 4 MB
__device__ __half g_w13h[(size_t)ENUM * 2 * IDIM * DDIM];        // 64 MB
__device__ __half g_w2h[(size_t)ENUM * DDIM * IDIM];             // 32 MB

// ---------------- helpers ----------------
__device__ __forceinline__ void mma16(float* c, const uint32_t* a, const uint32_t* b) {
    asm volatile(
        "mma.sync.aligned.m16n8k16.row.col.f32.f16.f16.f32 "
        "{%0,%1,%2,%3}, {%4,%5,%6,%7}, {%8,%9}, {%0,%1,%2,%3};\n"
        : "+f"(c[0]), "+f"(c[1]), "+f"(c[2]), "+f"(c[3])
        : "r"(a[0]), "r"(a[1]), "r"(a[2]), "r"(a[3]), "r"(b[0]), "r"(b[1]));
}
#define LDSM4(r0, r1, r2, r3, addr)                                        \
    asm volatile("ldmatrix.sync.aligned.m8n8.x4.shared.b16 {%0,%1,%2,%3}, [%4];" \
                 : "=r"(r0), "=r"(r1), "=r"(r2), "=r"(r3) : "r"(addr))
#define CP16(sm, gm) \
    asm volatile("cp.async.cg.shared.global [%0], [%1], 16;" :: "r"(sm), "l"(gm))
#define CP_COMMIT() asm volatile("cp.async.commit_group;")
#define CP_WAIT2()  asm volatile("cp.async.wait_group 2;")

// ---------------- prep: routing (block 0) + x/w13 convert (blocks 1..N) --------
__device__ __forceinline__ void cvt4(const float* s, __half* d, size_t i) {
    float4 v = ((const float4*)s)[i];
    __half2* o = (__half2*)(d + 4 * i);
    o[0] = __floats2half2_rn(v.x, v.y);
    o[1] = __floats2half2_rn(v.z, v.w);
}
__global__ void prep_kernel(const int* __restrict__ idx,
                            const float* __restrict__ x,
                            const float* __restrict__ w13) {
    if (blockIdx.x == 0) {
        // routing: counts -> offsets -> permutation (expert_indices is int32)
        __shared__ int sc[ENUM];
        __shared__ int scur[ENUM];
        int tid = threadIdx.x;
        if (tid < ENUM) sc[tid] = 0;
        __syncthreads();
        for (int p = tid; p < NPAIR; p += blockDim.x) atomicAdd(&sc[idx[p]], 1);
        __syncthreads();
        if (tid == 0) {
            int o = 0;
            for (int e = 0; e < ENUM; e++) {
                g_count[e] = sc[e]; g_off[e] = o; scur[e] = o; o += sc[e];
            }
        }
        __syncthreads();
        for (int p = tid; p < NPAIR; p += blockDim.x) {
            int pos = atomicAdd(&scur[idx[p]], 1);
            g_rowlist[pos] = p;
        }
    } else {
        size_t gid = (size_t)(blockIdx.x - 1) * blockDim.x + threadIdx.x;
        size_t gs  = (size_t)(gridDim.x - 1) * blockDim.x;
        for (size_t i = gid; i < (size_t)MTOK * DDIM / 4; i += gs)            cvt4(x,  g_x16,  i);
        for (size_t i = gid; i < (size_t)ENUM * 2 * IDIM * DDIM / 4; i += gs) cvt4(w13, g_w13h, i);
    }
}

// ncu captures the 4th launch: prep, dummy, dummy, GEMM1 <- profiled
__global__ void dummy_kernel() {}

// ---------------- GEMM1: h = x @ w13_e^T (both halves) + silu-gate ----------------
// CTA 128m x 128 gate-cols, BK=64, 4-stage cp.async, ks-pipelined fragments
// (R15 mainloop, untouched). blockIdx.z==0 CTAs instead convert w2 -> g_w2h,
// overlapping that HBM traffic (~24us) under gemm compute (DRAM only ~6% busy).
// z CTAs are scheduled first (z slowest-varying), so convert runs early.
#define G1_SROW  72
#define G1_STGH  ((128 + 256) * G1_SROW)          // halves/stage = 27648
#define G1_STGB  (G1_STGH * 2)                    // 55296 B
#define G1_SMEM  (4 * G1_STGB)                    // 221184 B (< 227 KB cap)
__global__ __launch_bounds__(256) void gemm1_kernel(const float* __restrict__ w2) {
    if (blockIdx.z == 0) {
        // w2 fp32 -> fp16 convert: 512 CTAs x 256 threads
        size_t gid = ((size_t)blockIdx.y * gridDim.x + blockIdx.x) * blockDim.x
                     + threadIdx.x;
        size_t gs  = (size_t)gridDim.x * gridDim.y * blockDim.x;
        for (size_t i = gid; i < (size_t)ENUM * DDIM * IDIM / 4; i += gs)
            cvt4(w2, g_w2h, i);
        return;
    }
    extern __shared__ __half sm1[];
    int e     = blockIdx.z - 1;
    int cnt   = g_count[e];
    int mbase = blockIdx.y * 128;
    if (mbase >= cnt) return;
    int nbase = blockIdx.x * 128;
    int off   = g_off[e];
    const char* xbase = (const char*)g_x16;
    const char* wbase = (const char*)(g_w13h + (size_t)e * 2 * IDIM * DDIM);

    int tid  = threadIdx.x;
    int lane = tid & 31, wp = tid >> 5;
    int wr = wp >> 2, wc = wp & 3;          // 2m x 4n warp grid
    int g  = lane >> 2, t = lane & 3;

    uint32_t sbase = (uint32_t)__cvta_generic_to_shared(sm1);

    // ---- cp.async fill metadata (u32 byte offsets; BK=64: 8 chunks/row) ----
    uint32_t a_goff[4], a_off[4];
#pragma unroll
    for (int i = 0; i < 4; i++) {
        int idx = tid + 256 * i, row = idx >> 3, c8 = idx & 7;
        int m = mbase + row;
        int tok = (m < cnt) ? (g_rowlist[off + m] >> 1) : 0;   // TOPK=2: token = pair>>1
        a_goff[i] = (uint32_t)(tok * DDIM + c8 * 8) * 2;
        a_off[i]  = (uint32_t)(row * G1_SROW + c8 * 8) * 2;
    }
    uint32_t b_goff[8], b_off[8];
#pragma unroll
    for (int i = 0; i < 8; i++) {
        int idx = tid + 256 * i, row = idx >> 3, c8 = idx & 7;
        b_goff[i] = (row < 128)
            ? (uint32_t)(((nbase + row) * DDIM + c8 * 8) * 2)
            : (uint32_t)((IDIM * DDIM + (size_t)(nbase + row - 128) * DDIM + c8 * 8) * 2);
        b_off[i] = (uint32_t)((128 + row) * G1_SROW + c8 * 8) * 2;
    }

#define G1_ISSUE(s, kt)                                                       \
    { uint32_t _sb = sbase + (s) * G1_STGB;                                   \
      uint32_t _k = (uint32_t)(kt) * 128;                                     \
      CP16(_sb + a_off[0], xbase + a_goff[0] + _k);                           \
      CP16(_sb + a_off[1], xbase + a_goff[1] + _k);                           \
      CP16(_sb + a_off[2], xbase + a_goff[2] + _k);                           \
      CP16(_sb + a_off[3], xbase + a_goff[3] + _k);                           \
      CP16(_sb + b_off[0], wbase + b_goff[0] + _k);                           \
      CP16(_sb + b_off[1], wbase + b_goff[1] + _k);                           \
      CP16(_sb + b_off[2], wbase + b_goff[2] + _k);                           \
      CP16(_sb + b_off[3], wbase + b_goff[3] + _k);                           \
      CP16(_sb + b_off[4], wbase + b_goff[4] + _k);                           \
      CP16(_sb + b_off[5], wbase + b_goff[5] + _k);                           \
      CP16(_sb + b_off[6], wbase + b_goff[6] + _k);                           \
      CP16(_sb + b_off[7], wbase + b_goff[7] + _k); }

    // ---- ldmatrix per-lane base addresses ----
    int lm = lane >> 3, ll = lane & 7;
    uint32_t a_lm[4], b1_lm[2], b3_lm[2];
#pragma unroll
    for (int mt = 0; mt < 4; mt++) {
        int row = wr * 64 + mt * 16 + (lm & 1) * 8 + ll;
        a_lm[mt] = (uint32_t)(row * G1_SROW + (lm >> 1) * 8) * 2;
    }
#pragma unroll
    for (int p = 0; p < 2; p++) {
        int row = wc * 32 + p * 16 + (lm >> 1) * 8 + ll;
        uint32_t o = (uint32_t)(row * G1_SROW + (lm & 1) * 8) * 2;
        b1_lm[p] = o + (uint32_t)(128 * G1_SROW) * 2;
        b3_lm[p] = o + (uint32_t)(256 * G1_SROW) * 2;
    }

    // double-buffered fragments
    uint32_t af[2][4][4], b1f[2][2][4], b3f[2][2][4];

#define G1_FRAGS(buf, sb, ko)                                                 \
    {                                                                         \
        _Pragma("unroll")                                                     \
        for (int mt = 0; mt < 4; mt++)                                        \
            LDSM4(af[buf][mt][0], af[buf][mt][1], af[buf][mt][2],             \
                  af[buf][mt][3], (sb) + a_lm[mt] + (ko));                    \
        _Pragma("unroll")                                                     \
        for (int p = 0; p < 2; p++) {                                         \
            LDSM4(b1f[buf][p][0], b1f[buf][p][1], b1f[buf][p][2],             \
                  b1f[buf][p][3], (sb) + b1_lm[p] + (ko));                    \
            LDSM4(b3f[buf][p][0], b3f[buf][p][1], b3f[buf][p][2],             \
                  b3f[buf][p][3], (sb) + b3_lm[p] + (ko));                    \
        }                                                                     \
    }

    float c[2][4][4][4];                     // [half][mt][nt][frag] = 128 regs
#pragma unroll
    for (int h = 0; h < 2; h++)
#pragma unroll
        for (int mt = 0; mt < 4; mt++)
#pragma unroll
            for (int nt = 0; nt < 4; nt++)
#pragma unroll
                for (int i = 0; i < 4; i++) c[h][mt][nt][i] = 0.f;

    const int nK = DDIM / 64;   // 16
    G1_ISSUE(0, 0) CP_COMMIT();
    G1_ISSUE(1, 1) CP_COMMIT();
    G1_ISSUE(2, 2) CP_COMMIT();

    for (int kt = 0; kt < nK; kt++) {
        CP_WAIT2();                          // own copies of stage kt done
        __syncthreads();                     // stage kt visible to all threads
        uint32_t sb = sbase + (kt & 3) * G1_STGB;
        G1_FRAGS(0, sb, 0)                   // ks=0 frags load under issue/commit
        if (kt + 3 < nK) { G1_ISSUE((kt + 3) & 3, kt + 3) }
        CP_COMMIT();                         // one group per iter keeps wait math exact
#pragma unroll
        for (int ks = 0; ks < 4; ks++) {
            int cur = ks & 1;
            if (ks < 3) { G1_FRAGS(cur ^ 1, sb, (uint32_t)(ks + 1) * 32) }
#pragma unroll
            for (int nt = 0; nt < 4; nt++) {
                const uint32_t* bb1 = &b1f[cur][nt >> 1][(nt & 1) * 2];
                const uint32_t* bb3 = &b3f[cur][nt >> 1][(nt & 1) * 2];
#pragma unroll
                for (int mt = 0; mt < 4; mt++) {
                    mma16(c[0][mt][nt], af[cur][mt], bb1);
                    mma16(c[1][mt][nt], af[cur][mt], bb3);
                }
            }
        }
    }

    // fused silu(x1)*x3 epilogue -> g_act (fp16, rows in grouped order)
    int rowbase = off + mbase;
#pragma unroll
    for (int mt = 0; mt < 4; mt++) {
        int r0 = wr * 64 + mt * 16 + g;
#pragma unroll
        for (int nt = 0; nt < 4; nt++) {
            int col = nbase + wc * 32 + nt * 8 + 2 * t;
            if (mbase + r0 < cnt) {
                float v1a = c[0][mt][nt][0], v3a = c[1][mt][nt][0];
                float v1b = c[0][mt][nt][1], v3b = c[1][mt][nt][1];
                float ga = v1a / (1.f + __expf(-v1a)) * v3a;
                float gb = v1b / (1.f + __expf(-v1b)) * v3b;
                *(__half2*)&g_act[(size_t)(rowbase + r0) * IDIM + col] =
                    __floats2half2_rn(ga, gb);
            }
            if (mbase + r0 + 8 < cnt) {
                float v1a = c[0][mt][nt][2], v3a = c[1][mt][nt][2];
                float v1b = c[0][mt][nt][3], v3b = c[1][mt][nt][3];
                float ga = v1a / (1.f + __expf(-v1a)) * v3a;
                float gb = v1b / (1.f + __expf(-v1b)) * v3b;
                *(__half2*)&g_act[(size_t)(rowbase + r0 + 8) * IDIM + col] =
                    __floats2half2_rn(ga, gb);
            }
        }
    }
}

// ---------------- GEMM2: out = g_act @ w2_e^T, scatter ----------------
// CTA 128m x 128n, BK=64, 4-stage cp.async + ks-pipelined frag double-buffering.
// (R15 mainloop, untouched.)
#define G2_SROW  72
#define G2_STGH  ((128 + 128) * G2_SROW)          // 18432 halves
#define G2_STGB  (G2_STGH * 2)                    // 36864 B
#define G2_SMEM  (4 * G2_STGB)                    // 147456 B
__global__ __launch_bounds__(256) void gemm2_kernel(float* __restrict__ out) {
    extern __shared__ __half sm2[];
    int e     = blockIdx.z;
    int cnt   = g_count[e];
    int mbase = blockIdx.y * 128;
    if (mbase >= cnt) return;
    int cbase = blockIdx.x * 128;
    int off   = g_off[e];
    const char* abase = (const char*)g_act;
    const char* wbase = (const char*)(g_w2h + (size_t)e * DDIM * IDIM);

    int tid  = threadIdx.x;
    int lane = tid & 31, wp = tid >> 5;
    int wr = wp >> 2, wc = wp & 3;
    int g  = lane >> 2, t = lane & 3;

    uint32_t sbase = (uint32_t)__cvta_generic_to_shared(sm2);

    uint32_t a_goff[4], a_off[4];
#pragma unroll
    for (int i = 0; i < 4; i++) {
        int idx = tid + 256 * i, row = idx >> 3, c8 = idx & 7;
        int ga = off + mbase + row;
        if (ga > NPAIR - 1) ga = NPAIR - 1;   // pad rows never stored
        a_goff[i] = (uint32_t)(((size_t)ga * IDIM + c8 * 8) * 2);
        a_off[i]  = (uint32_t)(row * G2_SROW + c8 * 8) * 2;
    }
    uint32_t b_goff[4], b_off[4];
#pragma unroll
    for (int i = 0; i < 4; i++) {
        int idx = tid + 256 * i, row = idx >> 3, c8 = idx & 7;
        b_goff[i] = (uint32_t)(((size_t)(cbase + row) * IDIM + c8 * 8) * 2);
        b_off[i]  = (uint32_t)((128 + row) * G2_SROW + c8 * 8) * 2;
    }

#define G2_ISSUE(s, kt)                                                       \
    { uint32_t _sb = sbase + (s) * G2_STGB;                                   \
      uint32_t _k = (uint32_t)(kt) * 128;                                     \
      CP16(_sb + a_off[0], abase + a_goff[0] + _k);                           \
      CP16(_sb + a_off[1], abase + a_goff[1] + _k);                           \
      CP16(_sb + a_off[2], abase + a_goff[2] + _k);                           \
      CP16(_sb + a_off[3], abase + a_goff[3] + _k);                           \
      CP16(_sb + b_off[0], wbase + b_goff[0] + _k);                           \
      CP16(_sb + b_off[1], wbase + b_goff[1] + _k);                           \
      CP16(_sb + b_off[2], wbase + b_goff[2] + _k);                           \
      CP16(_sb + b_off[3], wbase + b_goff[3] + _k); }

    int lm = lane >> 3, ll = lane & 7;
    uint32_t a_lm[4], b_lm[2];
#pragma unroll
    for (int mt = 0; mt < 4; mt++) {
        int row = wr * 64 + mt * 16 + (lm & 1) * 8 + ll;
        a_lm[mt] = (uint32_t)(row * G2_SROW + (lm >> 1) * 8) * 2;
    }
#pragma unroll
    for (int p = 0; p < 2; p++) {
        int row = wc * 32 + p * 16 + (lm >> 1) * 8 + ll;
        b_lm[p] = (uint32_t)((128 + row) * G2_SROW + (lm & 1) * 8) * 2;
    }

    uint32_t af[2][4][4], bf[2][2][4];

#define G2_FRAGS(buf, sb, ko)                                                 \
    {                                                                         \
        _Pragma("unroll")                                                     \
        for (int mt = 0; mt < 4; mt++)                                        \
            LDSM4(af[buf][mt][0], af[buf][mt][1], af[buf][mt][2],             \
                  af[buf][mt][3], (sb) + a_lm[mt] + (ko));                    \
        _Pragma("unroll")                                                     \
        for (int p = 0; p < 2; p++)                                           \
            LDSM4(bf[buf][p][0], bf[buf][p][1], bf[buf][p][2],                \
                  bf[buf][p][3], (sb) + b_lm[p] + (ko));                      \
    }

    float c[4][4][4];                        // [mt][nt][frag] = 64 regs
#pragma unroll
    for (int mt = 0; mt < 4; mt++)
#pragma unroll
        for (int nt = 0; nt < 4; nt++)
#pragma unroll
            for (int i = 0; i < 4; i++) c[mt][nt][i] = 0.f;

    const int nK = IDIM / 64;   // 32
    G2_ISSUE(0, 0) CP_COMMIT();
    G2_ISSUE(1, 1) CP_COMMIT();
    G2_ISSUE(2, 2) CP_COMMIT();

    for (int kt = 0; kt < nK; kt++) {
        CP_WAIT2();
        __syncthreads();
        uint32_t sb = sbase + (kt & 3) * G2_STGB;
        G2_FRAGS(0, sb, 0)
        if (kt + 3 < nK) { G2_ISSUE((kt + 3) & 3, kt + 3) }
        CP_COMMIT();
#pragma unroll
        for (int ks = 0; ks < 4; ks++) {
            int cur = ks & 1;
            if (ks < 3) { G2_FRAGS(cur ^ 1, sb, (uint32_t)(ks + 1) * 32) }
#pragma unroll
            for (int nt = 0; nt < 4; nt++) {
                const uint32_t* bb = &bf[cur][nt >> 1][(nt & 1) * 2];
#pragma unroll
                for (int mt = 0; mt < 4; mt++) mma16(c[mt][nt], af[cur][mt], bb);
            }
        }
    }

    // scatter epilogue: out[pair][col] (fp32)
#pragma unroll
    for (int mt = 0; mt < 4; mt++) {
        int r = wr * 64 + mt * 16 + g;
#pragma unroll
        for (int nt = 0; nt < 4; nt++) {
            int col = cbase + wc * 32 + nt * 8 + 2 * t;
            if (mbase + r < cnt) {
                int pair = g_rowlist[off + mbase + r];
                *(float2*)&out[(size_t)pair * DDIM + col] =
                    make_float2(c[mt][nt][0], c[mt][nt][1]);
            }
            if (mbase + r + 8 < cnt) {
                int pair = g_rowlist[off + mbase + r + 8];
                *(float2*)&out[(size_t)pair * DDIM + col] =
                    make_float2(c[mt][nt][2], c[mt][nt][3]);
            }
        }
    }
}

// ---------------- launch ----------------
extern "C" void kernel_launch(void* const* d_in, const int* in_sizes, int n_in,
                              void* d_out, int out_size) {
    (void)in_sizes; (void)n_in; (void)out_size;
    const float* x   = (const float*)d_in[0];
    const float* w13 = (const float*)d_in[1];
    const float* w2  = (const float*)d_in[2];
    const int*   idx = (const int*)d_in[3];
    float* out = (float*)d_out;

    cudaFuncSetAttribute(gemm1_kernel, cudaFuncAttributeMaxDynamicSharedMemorySize, G1_SMEM);
    cudaFuncSetAttribute(gemm2_kernel, cudaFuncAttributeMaxDynamicSharedMemorySize, G2_SMEM);

    prep_kernel<<<1025, 256>>>(idx, x, w13);       // block 0 routes, rest convert x+w13
    dummy_kernel<<<1, 32>>>();   // slot 2
    dummy_kernel<<<1, 32>>>();   // slot 3 -> gemm1 lands in profiled slot 4
    // z=0 slice converts w2 (scheduled first, overlaps under gemm compute);
    // z=1..8 are the 8 experts.
    gemm1_kernel<<<dim3(IDIM / 128, NPAIR / 128, ENUM + 1), 256, G1_SMEM>>>(w2);
    gemm2_kernel<<<dim3(DDIM / 128, NPAIR / 128, ENUM), 256, G2_SMEM>>>(out);
}